// round 10
// baseline (speedup 1.0000x reference)
#include <cuda_runtime.h>
#include <math.h>

// Fixed problem dims (B=4, N=512, C=128, ED=64, ATT=8, IN=128)
#define MAXB 4
#define MAXNM 511
#define MAXCH 32

typedef unsigned long long u64;

// ---------------- scratch (device globals) ----------------
__device__ float d_M[MAXB * 128 * 128];
__device__ float d_c[MAXB * 128];
__device__ float d_logits[MAXB * MAXNM * 128];
__device__ float d_etr[MAXB * MAXNM * 128];
__device__ float d_ntr[MAXB * MAXNM * 128];
__device__ float d_pm[MAXB * MAXCH * 128];
__device__ float d_ps[MAXB * MAXCH * 128];

__device__ __forceinline__ float geluf(float x) {
    return 0.5f * x * (1.0f + erff(x * 0.7071067811865476f));
}
__device__ __forceinline__ float rhof(float x) {
    return copysignf(sqrtf(fabsf(x)), x);
}
__device__ __forceinline__ void ffma2(u64& acc, u64 a, u64 b) {
    asm("fma.rn.f32x2 %0, %1, %2, %0;" : "+l"(acc) : "l"(a), "l"(b));
}
__device__ __forceinline__ u64 lo2(const float4& v) { return *(const u64*)&v.x; }
__device__ __forceinline__ u64 hi2(const float4& v) { return *(const u64*)&v.z; }
__device__ __forceinline__ float red2(u64 v) {
    return __uint_as_float((unsigned)v) + __uint_as_float((unsigned)(v >> 32));
}
__device__ __forceinline__ float dot4(float4 a, float4 b) {
    return a.x * b.x + a.y * b.y + a.z * b.z + a.w * b.w;
}

// ---- cp.async helpers ----
__device__ __forceinline__ unsigned smadr(const void* p) {
    return (unsigned)__cvta_generic_to_shared(p);
}
__device__ __forceinline__ void cpa16(unsigned dst, const void* src) {
    asm volatile("cp.async.cg.shared.global [%0], [%1], 16;"
                 :: "r"(dst), "l"(src));
}
__device__ __forceinline__ void cpa16z(unsigned dst, const void* src, bool p) {
    int sz = p ? 16 : 0;
    asm volatile("cp.async.cg.shared.global [%0], [%1], 16, %2;"
                 :: "r"(dst), "l"(src), "r"(sz));
}
#define CP_COMMIT() asm volatile("cp.async.commit_group;" ::: "memory")
#define CP_WAIT(N)  asm volatile("cp.async.wait_group %0;" :: "n"(N) : "memory")

// ---------------------------------------------------------------------------
// K1: fold q into M[b,e,d], c[b,e] for ALL batches per block.
// grid = 128, block = 512.
// ---------------------------------------------------------------------------
__global__ void __launch_bounds__(512)
k1_fold(const float* __restrict__ node,
        const float* __restrict__ Wq_w, const float* __restrict__ Wq_b,
        const float* __restrict__ Wk_w, const float* __restrict__ Wk_b,
        float* __restrict__ out_node, int B, int N) {
    __shared__ float wks[8][128];
    __shared__ float nds[MAXB][128];
    __shared__ float qv[MAXB][8];

    int e = blockIdx.x;
    int t = threadIdx.x;
    int lane = t & 31, w = t >> 5;

    if (blockIdx.x < (unsigned)B && t < 128) out_node[blockIdx.x * 128 + t] = 0.f;

    if (t < 256) {
        int a = t >> 5, d4 = t & 31;
        *(float4*)&wks[a][d4 * 4] =
            *(const float4*)&Wk_w[(size_t)((a << 7) + e) * 128 + d4 * 4];
    } else if (t < 384) {
        int q = t - 256;
        int b = q >> 5, d4 = q & 31;
        float4 v = make_float4(0.f, 0.f, 0.f, 0.f);
        if (b < B) v = *(const float4*)&node[(size_t)b * N * 128 + d4 * 4];
        *(float4*)&nds[b][d4 * 4] = v;
    }
    __syncthreads();

#pragma unroll
    for (int k = 0; k < 2; k++) {
        int p = w * 2 + k;
        int b = p >> 3, a = p & 7;
        int row = (a << 7) + e;
        float4 wq = *(const float4*)&Wq_w[(size_t)row * 128 + lane * 4];
        float4 nd = *(const float4*)&nds[b][lane * 4];
        float acc = dot4(wq, nd);
#pragma unroll
        for (int o = 16; o > 0; o >>= 1)
            acc += __shfl_down_sync(0xffffffffu, acc, o);
        if (lane == 0) qv[b][a] = acc + Wq_b[row];
    }
    __syncthreads();

    {
        int b = t >> 7, d = t & 127;
        if (b < B) {
            float acc = 0.f;
#pragma unroll
            for (int a = 0; a < 8; a++) acc += qv[b][a] * wks[a][d];
            d_M[(size_t)b * 16384 + e * 128 + d] = acc;
            if (d == 0) {
                float c = 0.f;
#pragma unroll
                for (int a = 0; a < 8; a++) c += qv[b][a] * Wk_b[(a << 7) + e];
                d_c[b * 128 + e] = c;
            }
        }
    }
}

// ---------------------------------------------------------------------------
// K23: qk + edge gelu + logits/etr/ntr + softmax partials.
// cp.async grouped staging overlapped with compute.
// grid = B*nblk, block = 512, smem 52928 floats.
// ---------------------------------------------------------------------------
__global__ void __launch_bounds__(512)
k23(const float* __restrict__ node,
    const float* __restrict__ edge,
    const float* __restrict__ emb,
    const float* __restrict__ Wew,
    const float* __restrict__ Web,
    const float* __restrict__ Wa,
    const float* __restrict__ nt_w, const float* __restrict__ nt_b,
    const float* __restrict__ et_w, const float* __restrict__ et_b,
    int N, int nblk) {
    extern __shared__ float sm[];
    float* Ms   = sm;                 // 16896 (128x132), later nt_w
    float* Wes  = Ms + 16896;         // 4352 (64x68)
    float* Wbs  = Wes + 4352;         // 4352
    float* Was  = Wbs + 4352;         // 8704 (128x68)
    float* ews  = Was + 8704;         // 8704
    float* nds  = ews + 8704;         // 2048 (16x128)
    float* e0s  = nds + 2048;         // 1024 (16x64)
    float* ems  = e0s + 1024;         // 1024
    float* cs   = ems + 1024;         // 128
    float* qks  = cs + 128;           // 2048
    float* pbuf = qks + 2048;         // 2048
    float* er   = pbuf + 2048;        // 1088 (16x68)
    float* redm = er + 1088;          // 256
    float* reds = redm + 256;         // 256

    int b  = blockIdx.x / nblk;
    int ch = blockIdx.x % nblk;
    int m0 = ch * 16;
    int t  = threadIdx.x;
    int NM = N - 1;

    // ---- async staging: g0 = Ms + nds + cs ----
    {
        const float4* src = (const float4*)(d_M + (size_t)b * 16384);
#pragma unroll
        for (int q = t; q < 4096; q += 512) {
            int e = q >> 5, d4 = q & 31;
            cpa16(smadr(&Ms[e * 132 + 4 * d4]), src + q);
        }
        int r = t >> 5, d4 = t & 31;
        int m = m0 + r;
        cpa16z(smadr(&nds[r * 128 + 4 * d4]),
               &node[((size_t)b * N + (m < NM ? m : 0) + 1) * 128 + 4 * d4],
               m < NM);
        if (t < 32) cpa16(smadr(&cs[t * 4]), &d_c[b * 128 + t * 4]);
    }
    CP_COMMIT();
    // ---- g1 = Wes/Wbs + e0s/ems ----
#pragma unroll
    for (int q = t; q < 1024; q += 512) {
        int j = q >> 4, d4 = q & 15;
        cpa16(smadr(&Wes[j * 68 + 4 * d4]), ((const float4*)Wew) + q);
        cpa16(smadr(&Wbs[j * 68 + 4 * d4]), ((const float4*)Web) + q);
    }
    {
        int q = t & 255;
        int r = q >> 4, d4 = q & 15;
        int m = m0 + r;
        size_t base = ((size_t)b * N * N + (size_t)((m < NM ? m : 0) + 1)) * 64 + 4 * d4;
        if (t < 256) cpa16z(smadr(&e0s[r * 64 + 4 * d4]), &edge[base], m < NM);
        else         cpa16z(smadr(&ems[r * 64 + 4 * d4]), &emb[base], m < NM);
    }
    CP_COMMIT();
    // ---- g2 = Was/ews ----
#pragma unroll
    for (int q = t; q < 2048; q += 512) {
        int i = q >> 4, d4 = q & 15;
        cpa16(smadr(&Was[i * 68 + 4 * d4]), ((const float4*)Wa) + q);
        cpa16(smadr(&ews[i * 68 + 4 * d4]), ((const float4*)et_w) + q);
    }
    CP_COMMIT();

    CP_WAIT(2);          // g0 complete
    __syncthreads();

    // ---- phase A: qk, 2 cols x 8 rows x ksplit2 on 256 threads ----
    {
        int tt = t & 255;
        int cp = tt & 63, rg = (tt >> 6) & 1, kh = tt >> 7;
        u64 a0[8] = {0,0,0,0,0,0,0,0}, a1[8] = {0,0,0,0,0,0,0,0};
        if (t < 256) {
            const float* w0p = Ms + cp * 132 + kh * 64;
            const float* w1p = Ms + (cp + 64) * 132 + kh * 64;
            const float* nbp = nds + rg * 8 * 128 + kh * 64;
#pragma unroll
            for (int d4 = 0; d4 < 16; d4++) {
                float4 w0 = *(const float4*)&w0p[4 * d4];
                float4 w1 = *(const float4*)&w1p[4 * d4];
                u64 w0l = lo2(w0), w0h = hi2(w0), w1l = lo2(w1), w1h = hi2(w1);
#pragma unroll
                for (int r = 0; r < 8; r++) {
                    float4 x4 = *(const float4*)&nbp[r * 128 + 4 * d4];
                    u64 xl = lo2(x4), xh = hi2(x4);
                    ffma2(a0[r], w0l, xl); ffma2(a0[r], w0h, xh);
                    ffma2(a1[r], w1l, xl); ffma2(a1[r], w1h, xh);
                }
            }
            if (kh == 1) {
#pragma unroll
                for (int r = 0; r < 8; r++) {
                    int rw = rg * 8 + r;
                    pbuf[rw * 128 + cp]      = red2(a0[r]);
                    pbuf[rw * 128 + cp + 64] = red2(a1[r]);
                }
            }
        }
        __syncthreads();
        // g3: prefetch nt_w into Ms (Ms reads finished at the sync above)
        if (t >= 256) {
#pragma unroll
            for (int q = t - 256; q < 4096; q += 256) {
                int i = q >> 5, d4 = q & 31;
                cpa16(smadr(&Ms[i * 132 + 4 * d4]), ((const float4*)nt_w) + q);
            }
        }
        CP_COMMIT();
        if (t < 128) {
            float c0 = cs[cp], c1 = cs[cp + 64];
#pragma unroll
            for (int r = 0; r < 8; r++) {
                int rw = rg * 8 + r;
                qks[rw * 128 + cp]      = red2(a0[r]) + pbuf[rw * 128 + cp] + c0;
                qks[rw * 128 + cp + 64] = red2(a1[r]) + pbuf[rw * 128 + cp + 64] + c1;
            }
        }
        CP_WAIT(2);      // g1 complete (g2, g3 may be pending)
        __syncthreads();
    }

    // ---- phase B: edge projections, 8 rows x ksplit2, 256 threads ----
    {
        int tt = t & 255;
        int j = tt & 63, rg = (tt >> 6) & 1, kh = tt >> 7;
        u64 ew2[8] = {0,0,0,0,0,0,0,0}, eb2[8] = {0,0,0,0,0,0,0,0};
        if (t < 256) {
            const float* wrow = Wes + j * 68 + kh * 32;
            const float* brow = Wbs + j * 68 + kh * 32;
            const float* xb = e0s + rg * 8 * 64 + kh * 32;
#pragma unroll
            for (int d4 = 0; d4 < 8; d4++) {
                float4 w4 = *(const float4*)&wrow[4 * d4];
                float4 b4 = *(const float4*)&brow[4 * d4];
                u64 wl = lo2(w4), wh = hi2(w4), bl = lo2(b4), bh = hi2(b4);
#pragma unroll
                for (int r = 0; r < 8; r++) {
                    float4 x4 = *(const float4*)&xb[r * 64 + 4 * d4];
                    u64 xl = lo2(x4), xh = hi2(x4);
                    ffma2(ew2[r], wl, xl); ffma2(ew2[r], wh, xh);
                    ffma2(eb2[r], bl, xl); ffma2(eb2[r], bh, xh);
                }
            }
            if (kh == 1) {
#pragma unroll
                for (int r = 0; r < 8; r++) {
                    int rw = rg * 8 + r;
                    pbuf[rw * 128 + j]      = red2(ew2[r]);
                    pbuf[rw * 128 + 64 + j] = red2(eb2[r]);
                }
            }
        }
        __syncthreads();
        if (t < 128) {
#pragma unroll
            for (int r = 0; r < 8; r++) {
                int rw = rg * 8 + r;
                int m = m0 + rw;
                float ew = red2(ew2[r]) + pbuf[rw * 128 + j];
                float eb = red2(eb2[r]) + pbuf[rw * 128 + 64 + j];
                float val = 0.f;
                if (m < NM) {
                    float x = rhof(qks[rw * 128 + j] * ew) + eb
                            + qks[rw * 128 + 64 + j] + ems[rw * 64 + j];
                    val = geluf(x);
                }
                er[rw * 68 + j] = val;
            }
        }
        CP_WAIT(0);      // g2 (Was/ews) and g3 (nt_w) complete
        __syncthreads();
    }

    // ---- phase C: C1 (logits+etr) on t<256 || C2 (ntr) on t in [256,384) ----
    if (t < 256) {
        int cp = t & 127, rg = t >> 7;
        u64 aa[8] = {0,0,0,0,0,0,0,0}, ae[8] = {0,0,0,0,0,0,0,0};
        const float* wa = Was + cp * 68;
        const float* we = ews + cp * 68;
        const float* xb = er + rg * 8 * 68;
#pragma unroll
        for (int d4 = 0; d4 < 16; d4++) {
            float4 a4 = *(const float4*)&wa[4 * d4];
            float4 c4 = *(const float4*)&we[4 * d4];
            u64 al = lo2(a4), ah = hi2(a4), cl = lo2(c4), chh = hi2(c4);
#pragma unroll
            for (int r = 0; r < 8; r++) {
                float4 x4 = *(const float4*)&xb[r * 68 + 4 * d4];
                u64 xl = lo2(x4), xh = hi2(x4);
                ffma2(aa[r], al, xl); ffma2(aa[r], ah, xh);
                ffma2(ae[r], cl, xl); ffma2(ae[r], chh, xh);
            }
        }
        float be = et_b[cp];
        float lg[8];
        float lm = -3.4e38f;
#pragma unroll
        for (int r = 0; r < 8; r++) {
            lg[r] = red2(aa[r]);
            int m = m0 + rg * 8 + r;
            if (m < NM) {
                size_t o = ((size_t)b * NM + m) * 128;
                d_logits[o + cp] = lg[r];
                d_etr[o + cp]    = red2(ae[r]) + be;
                lm = fmaxf(lm, lg[r]);
            }
        }
        float ls = 0.f;
#pragma unroll
        for (int r = 0; r < 8; r++) {
            int m = m0 + rg * 8 + r;
            if (m < NM) ls += expf(lg[r] - lm);
        }
        redm[cp * 2 + rg] = lm;
        reds[cp * 2 + rg] = ls;
    } else if (t < 384) {
        int tt = t - 256;
        int cp = tt & 63, rg = tt >> 6;
        u64 an0[8] = {0,0,0,0,0,0,0,0}, an1[8] = {0,0,0,0,0,0,0,0};
        const float* wn0 = Ms + cp * 132;
        const float* wn1 = Ms + (cp + 64) * 132;
        const float* xb = nds + rg * 8 * 128;
#pragma unroll 8
        for (int d4 = 0; d4 < 32; d4++) {
            float4 a4 = *(const float4*)&wn0[4 * d4];
            float4 b4 = *(const float4*)&wn1[4 * d4];
            u64 al = lo2(a4), ah = hi2(a4), bl = lo2(b4), bh = hi2(b4);
#pragma unroll
            for (int r = 0; r < 8; r++) {
                float4 x4 = *(const float4*)&xb[r * 128 + 4 * d4];
                u64 xl = lo2(x4), xh = hi2(x4);
                ffma2(an0[r], al, xl); ffma2(an0[r], ah, xh);
                ffma2(an1[r], bl, xl); ffma2(an1[r], bh, xh);
            }
        }
        float bn0 = nt_b[cp], bn1 = nt_b[cp + 64];
#pragma unroll
        for (int r = 0; r < 8; r++) {
            int m = m0 + rg * 8 + r;
            if (m < NM) {
                size_t o = ((size_t)b * NM + m) * 128;
                d_ntr[o + cp]      = red2(an0[r]) + bn0;
                d_ntr[o + cp + 64] = red2(an1[r]) + bn1;
            }
        }
    }
    __syncthreads();

    if (t < 128) {
        int i = t;
        float m = fmaxf(redm[i * 2], redm[i * 2 + 1]);
        float s = reds[i * 2] * expf(redm[i * 2] - m)
                + reds[i * 2 + 1] * expf(redm[i * 2 + 1] - m);
        d_pm[(b * nblk + ch) * 128 + i] = m;
        d_ps[(b * nblk + ch) * 128 + i] = s;
    }
}

// ---------------------------------------------------------------------------
// K5: softmax combine + alpha + v + h1 gemm/gelu + h2 gemm + stores.
// All global reads prefetched via cp.async groups.
// grid = B*nblk, block = 512, smem 51200 floats (200 KB).
// ---------------------------------------------------------------------------
__global__ void __launch_bounds__(512)
k5(const float* __restrict__ h1_w, const float* __restrict__ h1_b,
   const float* __restrict__ h2_w, const float* __restrict__ h2_b,
   float* __restrict__ out_et, float* __restrict__ out_tmp,
   float* __restrict__ out_node, int N, int nblk, float scaler) {
    extern __shared__ float sm[];
    float* H    = sm;                 // 33280 (h1_w, later h2_w)
    float* v    = H + 33280;          // 4160 (16x260)
    float* als  = v + 4160;           // 2048
    float* pbuf = als + 2048;         // 2048 (logits stage, then reductions)
    float* tr   = pbuf + 2048;        // 4096 (etr | ntr stage)
    float* mxs  = tr + 4096;          // 128
    float* invs = mxs + 128;          // 128
    float* redm = invs + 128;         // 512
    float* reds = redm + 512;         // 512
    float* gs   = reds + 512;         // 2112 (16x132)
    float* qo   = gs + 2112;          // 2176 (128x17)

    int b  = blockIdx.x / nblk;
    int m0 = (blockIdx.x % nblk) * 16;
    int t  = threadIdx.x;
    int NM = N - 1;

    // ---- g0 = logits -> pbuf ----
    {
        int r = t >> 5, d4 = t & 31;
        int m = m0 + r;
        cpa16z(smadr(&pbuf[r * 128 + 4 * d4]),
               &d_logits[((size_t)b * NM + (m < NM ? m : 0)) * 128 + 4 * d4],
               m < NM);
    }
    CP_COMMIT();
    // ---- g1 = etr + ntr -> tr ----
#pragma unroll
    for (int q = t; q < 1024; q += 512) {
        int half = q >> 9, r = (q >> 5) & 15, d4 = q & 31;
        int m = m0 + r;
        size_t o = ((size_t)b * NM + (m < NM ? m : 0)) * 128 + 4 * d4;
        const float* src = half ? &d_ntr[o] : &d_etr[o];
        cpa16z(smadr(&tr[half * 2048 + r * 128 + 4 * d4]), src, m < NM);
    }
    CP_COMMIT();
    // ---- g2 = h1_w -> H ----
#pragma unroll
    for (int q = t; q < 8192; q += 512) {
        int i = q >> 6, d4 = q & 63;
        cpa16(smadr(&H[i * 260 + 4 * d4]), ((const float4*)h1_w) + q);
    }
    CP_COMMIT();

    // ---- softmax combine (normal loads; overlaps the async streams) ----
    {
        int i = t & 127, cg = t >> 7;
        float m = -3.4e38f, s = 0.f;
        for (int chh = cg; chh < nblk; chh += 4) {
            float pm = d_pm[(b * nblk + chh) * 128 + i];
            float ps = d_ps[(b * nblk + chh) * 128 + i];
            float nm = fmaxf(m, pm);
            s = s * expf(m - nm) + ps * expf(pm - nm);
            m = nm;
        }
        redm[i * 4 + cg] = m;
        reds[i * 4 + cg] = s;
    }
    __syncthreads();
    if (t < 128) {
        int i = t;
        float m = -3.4e38f;
#pragma unroll
        for (int g = 0; g < 4; g++) m = fmaxf(m, redm[i * 4 + g]);
        float s = 0.f;
#pragma unroll
        for (int g = 0; g < 4; g++) s += reds[i * 4 + g] * expf(redm[i * 4 + g] - m);
        mxs[i]  = m;
        invs[i] = 1.f / s;
    }
    CP_WAIT(2);          // g0 (logits) complete
    __syncthreads();

    // ---- alpha (reads staged logits from smem) ----
#pragma unroll
    for (int q = t; q < 2048; q += 512) {
        int r = q >> 7, i = q & 127;
        int m = m0 + r;
        float a = 0.f;
        if (m < NM) a = expf(pbuf[q] - mxs[i]) * invs[i];
        als[q] = a;
    }
    CP_WAIT(1);          // g1 (etr/ntr) complete
    __syncthreads();

    // ---- v = [etr*a | ntr*a] from staged tr ----
#pragma unroll
    for (int q = t; q < 4096; q += 512) {
        int r = q >> 8, d = q & 255;
        int dd = d & 127;
        v[r * 260 + d] = tr[(d < 128 ? 0 : 2048) + r * 128 + dd] * als[r * 128 + dd];
    }
    CP_WAIT(0);          // g2 (h1_w) complete
    __syncthreads();

    // ---- h1 GEMM (t<256) || et_p store (t>=256) ----
    {
        int tt = t & 255;
        int cp = tt & 63, rg = (tt >> 6) & 1, kh = tt >> 7;
        u64 a0[8] = {0,0,0,0,0,0,0,0}, a1[8] = {0,0,0,0,0,0,0,0};
        if (t < 256) {
            const float* w0p = H + cp * 260 + kh * 128;
            const float* w1p = H + (cp + 64) * 260 + kh * 128;
            const float* vb  = v + rg * 8 * 260 + kh * 128;
#pragma unroll 8
            for (int d4 = 0; d4 < 32; d4++) {
                float4 w0 = *(const float4*)&w0p[4 * d4];
                float4 w1 = *(const float4*)&w1p[4 * d4];
                u64 w0l = lo2(w0), w0h = hi2(w0), w1l = lo2(w1), w1h = hi2(w1);
#pragma unroll
                for (int r = 0; r < 8; r++) {
                    float4 x4 = *(const float4*)&vb[r * 260 + 4 * d4];
                    u64 xl = lo2(x4), xh = hi2(x4);
                    ffma2(a0[r], w0l, xl); ffma2(a0[r], w0h, xh);
                    ffma2(a1[r], w1l, xl); ffma2(a1[r], w1h, xh);
                }
            }
            if (kh == 1) {
#pragma unroll
                for (int r = 0; r < 8; r++) {
                    int rw = rg * 8 + r;
                    pbuf[rw * 128 + cp]      = red2(a0[r]);
                    pbuf[rw * 128 + cp + 64] = red2(a1[r]);
                }
            }
        } else {
#pragma unroll
            for (int q = t - 256; q < 2048; q += 256) {
                int i = q >> 4, mr = q & 15;
                int m = m0 + mr;
                if (m < NM) out_et[((size_t)b * 128 + i) * NM + m] = v[mr * 260 + i];
            }
        }
        __syncthreads();
        // g3: prefetch h2_w into H (h1 reads of H done at sync above)
        if (t >= 256) {
#pragma unroll
            for (int q = t - 256; q < 4096; q += 256) {
                int i = q >> 5, d4 = q & 31;
                cpa16(smadr(&H[i * 132 + 4 * d4]), ((const float4*)h2_w) + q);
            }
        }
        CP_COMMIT();
        if (t < 128) {
            float b0 = h1_b[cp], b1 = h1_b[cp + 64];
#pragma unroll
            for (int r = 0; r < 8; r++) {
                int rw = rg * 8 + r;
                int m = m0 + rw;
                float g0 = red2(a0[r]) + pbuf[rw * 128 + cp] + b0;
                float g1 = red2(a1[r]) + pbuf[rw * 128 + cp + 64] + b1;
                gs[rw * 132 + cp]      = (m < NM) ? geluf(g0) : 0.f;
                gs[rw * 132 + cp + 64] = (m < NM) ? geluf(g1) : 0.f;
            }
        }
        CP_WAIT(0);      // g3 (h2_w) complete
        __syncthreads();
    }

    // ---- h2 GEMM (t<256, 2 cols x 8 rows x ksplit2) ----
    {
        int tt = t & 255;
        int cp = tt & 63, rg = (tt >> 6) & 1, kh = tt >> 7;
        u64 a0[8] = {0,0,0,0,0,0,0,0}, a1[8] = {0,0,0,0,0,0,0,0};
        if (t < 256) {
            const float* w0p = H + cp * 132 + kh * 64;
            const float* w1p = H + (cp + 64) * 132 + kh * 64;
            const float* gb  = gs + rg * 8 * 132 + kh * 64;
#pragma unroll
            for (int d4 = 0; d4 < 16; d4++) {
                float4 w0 = *(const float4*)&w0p[4 * d4];
                float4 w1 = *(const float4*)&w1p[4 * d4];
                u64 w0l = lo2(w0), w0h = hi2(w0), w1l = lo2(w1), w1h = hi2(w1);
#pragma unroll
                for (int r = 0; r < 8; r++) {
                    float4 x4 = *(const float4*)&gb[r * 132 + 4 * d4];
                    u64 xl = lo2(x4), xh = hi2(x4);
                    ffma2(a0[r], w0l, xl); ffma2(a0[r], w0h, xh);
                    ffma2(a1[r], w1l, xl); ffma2(a1[r], w1h, xh);
                }
            }
            if (kh == 1) {
#pragma unroll
                for (int r = 0; r < 8; r++) {
                    int rw = rg * 8 + r;
                    pbuf[rw * 128 + cp]      = red2(a0[r]);
                    pbuf[rw * 128 + cp + 64] = red2(a1[r]);
                }
            }
        }
        __syncthreads();
        if (t < 128) {
            float b0 = h2_b[cp], b1 = h2_b[cp + 64];
#pragma unroll
            for (int r = 0; r < 8; r++) {
                int rw = rg * 8 + r;
                int m = m0 + rw;
                float t0 = (m < NM) ? red2(a0[r]) + pbuf[rw * 128 + cp] + b0 : 0.f;
                float t1 = (m < NM) ? red2(a1[r]) + pbuf[rw * 128 + cp + 64] + b1 : 0.f;
                qo[cp * 17 + rw]        = t0;
                qo[(cp + 64) * 17 + rw] = t1;
            }
        }
        __syncthreads();
    }

#pragma unroll
    for (int q = t; q < 2048; q += 512) {
        int i = q >> 4, mr = q & 15;
        int m = m0 + mr;
        if (m < NM) out_tmp[((size_t)b * 128 + i) * NM + m] = qo[i * 17 + mr];
    }
    if (t < 128) {
        int i = t;
        float s = 0.f;
#pragma unroll
        for (int mr = 0; mr < 16; mr++) s += qo[i * 17 + mr];
        atomicAdd(&out_node[b * 128 + i], s * scaler);
    }
}

// ---------------------------------------------------------------------------
extern "C" void kernel_launch(void* const* d_in, const int* in_sizes, int n_in,
                              void* d_out, int out_size) {
    const float* node = (const float*)d_in[0];
    const float* edge = (const float*)d_in[1];
    const float* emb  = (const float*)d_in[2];
    const float* Wq_w = (const float*)d_in[3];
    const float* Wq_b = (const float*)d_in[4];
    const float* Wk_w = (const float*)d_in[5];
    const float* Wk_b = (const float*)d_in[6];
    const float* Wew  = (const float*)d_in[7];
    const float* Web  = (const float*)d_in[8];
    const float* Wa   = (const float*)d_in[9];
    const float* nt_w = (const float*)d_in[10];
    const float* nt_b = (const float*)d_in[11];
    const float* et_w = (const float*)d_in[12];
    const float* et_b = (const float*)d_in[13];
    const float* h1_w = (const float*)d_in[14];
    const float* h1_b = (const float*)d_in[15];
    const float* h2_w = (const float*)d_in[16];
    const float* h2_b = (const float*)d_in[17];

    long n_node = in_sizes[0];
    long n_edge = in_sizes[1];
    int N = (int)((2L * n_edge) / n_node);   // 512
    int B = (int)(n_node / ((long)N * 128)); // 4
    int NM = N - 1;
    int nblk = (NM + 15) / 16;               // 32

    float* out      = (float*)d_out;
    float* out_node = out;
    float* out_tmp  = out + (size_t)B * 128;
    float* out_et   = out_tmp + (size_t)B * 128 * NM;

    const int SM23 = 52928 * 4;
    const int SM5  = 51200 * 4;

    cudaFuncSetAttribute(k23, cudaFuncAttributeMaxDynamicSharedMemorySize, SM23);
    cudaFuncSetAttribute(k5,  cudaFuncAttributeMaxDynamicSharedMemorySize, SM5);

    float scaler = 2.0f / sqrtf(128.0f);

    k1_fold<<<128, 512>>>(node, Wq_w, Wq_b, Wk_w, Wk_b, out_node, B, N);
    k23<<<B * nblk, 512, SM23>>>(node, edge, emb, Wew, Web, Wa,
                                 nt_w, nt_b, et_w, et_b, N, nblk);
    k5<<<B * nblk, 512, SM5>>>(h1_w, h1_b, h2_w, h2_b,
                               out_et, out_tmp, out_node, N, nblk, scaler);
}

// round 11
// speedup vs baseline: 1.0635x; 1.0635x over previous
#include <cuda_runtime.h>
#include <math.h>

// Fixed problem dims (B=4, N=512, C=128, ED=64, ATT=8, IN=128)
#define MAXB 4
#define MAXNM 511
#define MAXCH 32

typedef unsigned long long u64;

// ---------------- scratch (device globals) ----------------
__device__ float d_M[MAXB * 128 * 128];
__device__ float d_c[MAXB * 128];
__device__ float d_logits[MAXB * MAXNM * 128];
__device__ float d_etr[MAXB * MAXNM * 128];
__device__ float d_ntr[MAXB * MAXNM * 128];
__device__ float d_pm[MAXB * MAXCH * 128];
__device__ float d_ps[MAXB * MAXCH * 128];

__device__ __forceinline__ float geluf(float x) {
    return 0.5f * x * (1.0f + erff(x * 0.7071067811865476f));
}
__device__ __forceinline__ float rhof(float x) {
    return copysignf(sqrtf(fabsf(x)), x);
}
__device__ __forceinline__ void ffma2(u64& acc, u64 a, u64 b) {
    asm("fma.rn.f32x2 %0, %1, %2, %0;" : "+l"(acc) : "l"(a), "l"(b));
}
__device__ __forceinline__ u64 lo2(const float4& v) { return *(const u64*)&v.x; }
__device__ __forceinline__ u64 hi2(const float4& v) { return *(const u64*)&v.z; }
__device__ __forceinline__ float red2(u64 v) {
    return __uint_as_float((unsigned)v) + __uint_as_float((unsigned)(v >> 32));
}
__device__ __forceinline__ float dot4(float4 a, float4 b) {
    return a.x * b.x + a.y * b.y + a.z * b.z + a.w * b.w;
}

// ---- cp.async helpers ----
__device__ __forceinline__ unsigned smadr(const void* p) {
    return (unsigned)__cvta_generic_to_shared(p);
}
__device__ __forceinline__ void cpa16(unsigned dst, const void* src) {
    asm volatile("cp.async.cg.shared.global [%0], [%1], 16;"
                 :: "r"(dst), "l"(src));
}
__device__ __forceinline__ void cpa16z(unsigned dst, const void* src, bool p) {
    int sz = p ? 16 : 0;
    asm volatile("cp.async.cg.shared.global [%0], [%1], 16, %2;"
                 :: "r"(dst), "l"(src), "r"(sz));
}
#define CP_COMMIT() asm volatile("cp.async.commit_group;" ::: "memory")
#define CP_WAIT(N)  asm volatile("cp.async.wait_group %0;" :: "n"(N) : "memory")

// ---------------------------------------------------------------------------
// K1: fold q into M[b,e,d], c[b,e] for ALL batches per block.
// grid = 128, block = 512.
// ---------------------------------------------------------------------------
__global__ void __launch_bounds__(512)
k1_fold(const float* __restrict__ node,
        const float* __restrict__ Wq_w, const float* __restrict__ Wq_b,
        const float* __restrict__ Wk_w, const float* __restrict__ Wk_b,
        float* __restrict__ out_node, int B, int N) {
    __shared__ float wks[8][128];
    __shared__ float nds[MAXB][128];
    __shared__ float qv[MAXB][8];

    int e = blockIdx.x;
    int t = threadIdx.x;
    int lane = t & 31, w = t >> 5;

    if (blockIdx.x < (unsigned)B && t < 128) out_node[blockIdx.x * 128 + t] = 0.f;

    if (t < 256) {
        int a = t >> 5, d4 = t & 31;
        *(float4*)&wks[a][d4 * 4] =
            *(const float4*)&Wk_w[(size_t)((a << 7) + e) * 128 + d4 * 4];
    } else if (t < 384) {
        int q = t - 256;
        int b = q >> 5, d4 = q & 31;
        float4 v = make_float4(0.f, 0.f, 0.f, 0.f);
        if (b < B) v = *(const float4*)&node[(size_t)b * N * 128 + d4 * 4];
        *(float4*)&nds[b][d4 * 4] = v;
    }
    __syncthreads();

#pragma unroll
    for (int k = 0; k < 2; k++) {
        int p = w * 2 + k;
        int b = p >> 3, a = p & 7;
        int row = (a << 7) + e;
        float4 wq = *(const float4*)&Wq_w[(size_t)row * 128 + lane * 4];
        float4 nd = *(const float4*)&nds[b][lane * 4];
        float acc = dot4(wq, nd);
#pragma unroll
        for (int o = 16; o > 0; o >>= 1)
            acc += __shfl_down_sync(0xffffffffu, acc, o);
        if (lane == 0) qv[b][a] = acc + Wq_b[row];
    }
    __syncthreads();

    {
        int b = t >> 7, d = t & 127;
        if (b < B) {
            float acc = 0.f;
#pragma unroll
            for (int a = 0; a < 8; a++) acc += qv[b][a] * wks[a][d];
            d_M[(size_t)b * 16384 + e * 128 + d] = acc;
            if (d == 0) {
                float c = 0.f;
#pragma unroll
                for (int a = 0; a < 8; a++) c += qv[b][a] * Wk_b[(a << 7) + e];
                d_c[b * 128 + e] = c;
            }
        }
    }
}

// ---------------------------------------------------------------------------
// K23: qk + edge gelu + logits/etr/ntr + softmax partials.
// Phase C now uses all 512 threads (C1 on 256 || C2 ntr on 256 w/ kh-split).
// grid = B*nblk, block = 512, smem 52928 floats.
// ---------------------------------------------------------------------------
__global__ void __launch_bounds__(512)
k23(const float* __restrict__ node,
    const float* __restrict__ edge,
    const float* __restrict__ emb,
    const float* __restrict__ Wew,
    const float* __restrict__ Web,
    const float* __restrict__ Wa,
    const float* __restrict__ nt_w, const float* __restrict__ nt_b,
    const float* __restrict__ et_w, const float* __restrict__ et_b,
    int N, int nblk) {
    extern __shared__ float sm[];
    float* Ms   = sm;                 // 16896 (128x132), later nt_w
    float* Wes  = Ms + 16896;         // 4352
    float* Wbs  = Wes + 4352;         // 4352
    float* Was  = Wbs + 4352;         // 8704
    float* ews  = Was + 8704;         // 8704
    float* nds  = ews + 8704;         // 2048
    float* e0s  = nds + 2048;         // 1024
    float* ems  = e0s + 1024;         // 1024
    float* cs   = ems + 1024;         // 128
    float* qks  = cs + 128;           // 2048
    float* pbuf = qks + 2048;         // 2048
    float* er   = pbuf + 2048;        // 1088
    float* redm = er + 1088;          // 256
    float* reds = redm + 256;         // 256

    int b  = blockIdx.x / nblk;
    int ch = blockIdx.x % nblk;
    int m0 = ch * 16;
    int t  = threadIdx.x;
    int NM = N - 1;

    // ---- async staging: g0 = Ms + nds + cs ----
    {
        const float4* src = (const float4*)(d_M + (size_t)b * 16384);
#pragma unroll
        for (int q = t; q < 4096; q += 512) {
            int e = q >> 5, d4 = q & 31;
            cpa16(smadr(&Ms[e * 132 + 4 * d4]), src + q);
        }
        int r = t >> 5, d4 = t & 31;
        int m = m0 + r;
        cpa16z(smadr(&nds[r * 128 + 4 * d4]),
               &node[((size_t)b * N + (m < NM ? m : 0) + 1) * 128 + 4 * d4],
               m < NM);
        if (t < 32) cpa16(smadr(&cs[t * 4]), &d_c[b * 128 + t * 4]);
    }
    CP_COMMIT();
    // ---- g1 = Wes/Wbs + e0s/ems ----
#pragma unroll
    for (int q = t; q < 1024; q += 512) {
        int j = q >> 4, d4 = q & 15;
        cpa16(smadr(&Wes[j * 68 + 4 * d4]), ((const float4*)Wew) + q);
        cpa16(smadr(&Wbs[j * 68 + 4 * d4]), ((const float4*)Web) + q);
    }
    {
        int q = t & 255;
        int r = q >> 4, d4 = q & 15;
        int m = m0 + r;
        size_t base = ((size_t)b * N * N + (size_t)((m < NM ? m : 0) + 1)) * 64 + 4 * d4;
        if (t < 256) cpa16z(smadr(&e0s[r * 64 + 4 * d4]), &edge[base], m < NM);
        else         cpa16z(smadr(&ems[r * 64 + 4 * d4]), &emb[base], m < NM);
    }
    CP_COMMIT();
    // ---- g2 = Was/ews ----
#pragma unroll
    for (int q = t; q < 2048; q += 512) {
        int i = q >> 4, d4 = q & 15;
        cpa16(smadr(&Was[i * 68 + 4 * d4]), ((const float4*)Wa) + q);
        cpa16(smadr(&ews[i * 68 + 4 * d4]), ((const float4*)et_w) + q);
    }
    CP_COMMIT();

    CP_WAIT(2);          // g0 complete
    __syncthreads();

    // ---- phase A: qk, 2 cols x 8 rows x ksplit2 on 256 threads ----
    {
        int tt = t & 255;
        int cp = tt & 63, rg = (tt >> 6) & 1, kh = tt >> 7;
        u64 a0[8] = {0,0,0,0,0,0,0,0}, a1[8] = {0,0,0,0,0,0,0,0};
        if (t < 256) {
            const float* w0p = Ms + cp * 132 + kh * 64;
            const float* w1p = Ms + (cp + 64) * 132 + kh * 64;
            const float* nbp = nds + rg * 8 * 128 + kh * 64;
#pragma unroll
            for (int d4 = 0; d4 < 16; d4++) {
                float4 w0 = *(const float4*)&w0p[4 * d4];
                float4 w1 = *(const float4*)&w1p[4 * d4];
                u64 w0l = lo2(w0), w0h = hi2(w0), w1l = lo2(w1), w1h = hi2(w1);
#pragma unroll
                for (int r = 0; r < 8; r++) {
                    float4 x4 = *(const float4*)&nbp[r * 128 + 4 * d4];
                    u64 xl = lo2(x4), xh = hi2(x4);
                    ffma2(a0[r], w0l, xl); ffma2(a0[r], w0h, xh);
                    ffma2(a1[r], w1l, xl); ffma2(a1[r], w1h, xh);
                }
            }
            if (kh == 1) {
#pragma unroll
                for (int r = 0; r < 8; r++) {
                    int rw = rg * 8 + r;
                    pbuf[rw * 128 + cp]      = red2(a0[r]);
                    pbuf[rw * 128 + cp + 64] = red2(a1[r]);
                }
            }
        }
        __syncthreads();
        // g3: prefetch nt_w into Ms (Ms reads finished at the sync above)
        if (t >= 256) {
#pragma unroll
            for (int q = t - 256; q < 4096; q += 256) {
                int i = q >> 5, d4 = q & 31;
                cpa16(smadr(&Ms[i * 132 + 4 * d4]), ((const float4*)nt_w) + q);
            }
        }
        CP_COMMIT();
        if (t < 128) {
            float c0 = cs[cp], c1 = cs[cp + 64];
#pragma unroll
            for (int r = 0; r < 8; r++) {
                int rw = rg * 8 + r;
                qks[rw * 128 + cp]      = red2(a0[r]) + pbuf[rw * 128 + cp] + c0;
                qks[rw * 128 + cp + 64] = red2(a1[r]) + pbuf[rw * 128 + cp + 64] + c1;
            }
        }
        CP_WAIT(2);      // g1 complete (g2, g3 may be pending)
        __syncthreads();
    }

    // ---- phase B: edge projections, 8 rows x ksplit2, 256 threads ----
    {
        int tt = t & 255;
        int j = tt & 63, rg = (tt >> 6) & 1, kh = tt >> 7;
        u64 ew2[8] = {0,0,0,0,0,0,0,0}, eb2[8] = {0,0,0,0,0,0,0,0};
        if (t < 256) {
            const float* wrow = Wes + j * 68 + kh * 32;
            const float* brow = Wbs + j * 68 + kh * 32;
            const float* xb = e0s + rg * 8 * 64 + kh * 32;
#pragma unroll
            for (int d4 = 0; d4 < 8; d4++) {
                float4 w4 = *(const float4*)&wrow[4 * d4];
                float4 b4 = *(const float4*)&brow[4 * d4];
                u64 wl = lo2(w4), wh = hi2(w4), bl = lo2(b4), bh = hi2(b4);
#pragma unroll
                for (int r = 0; r < 8; r++) {
                    float4 x4 = *(const float4*)&xb[r * 64 + 4 * d4];
                    u64 xl = lo2(x4), xh = hi2(x4);
                    ffma2(ew2[r], wl, xl); ffma2(ew2[r], wh, xh);
                    ffma2(eb2[r], bl, xl); ffma2(eb2[r], bh, xh);
                }
            }
            if (kh == 1) {
#pragma unroll
                for (int r = 0; r < 8; r++) {
                    int rw = rg * 8 + r;
                    pbuf[rw * 128 + j]      = red2(ew2[r]);
                    pbuf[rw * 128 + 64 + j] = red2(eb2[r]);
                }
            }
        }
        __syncthreads();
        if (t < 128) {
#pragma unroll
            for (int r = 0; r < 8; r++) {
                int rw = rg * 8 + r;
                int m = m0 + rw;
                float ew = red2(ew2[r]) + pbuf[rw * 128 + j];
                float eb = red2(eb2[r]) + pbuf[rw * 128 + 64 + j];
                float val = 0.f;
                if (m < NM) {
                    float x = rhof(qks[rw * 128 + j] * ew) + eb
                            + qks[rw * 128 + 64 + j] + ems[rw * 64 + j];
                    val = geluf(x);
                }
                er[rw * 68 + j] = val;
            }
        }
        CP_WAIT(0);      // g2 (Was/ews) and g3 (nt_w) complete
        __syncthreads();
    }

    // ---- phase C: C1 (logits+etr) on t<256 || C2 (ntr, kh-split) on t>=256 --
    {
        u64 an0[8] = {0,0,0,0,0,0,0,0}, an1[8] = {0,0,0,0,0,0,0,0};
        int c2cp = 0, c2rg = 0, c2kh = 0;
        if (t < 256) {
            int cp = t & 127, rg = t >> 7;
            u64 aa[8] = {0,0,0,0,0,0,0,0}, ae[8] = {0,0,0,0,0,0,0,0};
            const float* wa = Was + cp * 68;
            const float* we = ews + cp * 68;
            const float* xb = er + rg * 8 * 68;
#pragma unroll
            for (int d4 = 0; d4 < 16; d4++) {
                float4 a4 = *(const float4*)&wa[4 * d4];
                float4 c4 = *(const float4*)&we[4 * d4];
                u64 al = lo2(a4), ah = hi2(a4), cl = lo2(c4), chh = hi2(c4);
#pragma unroll
                for (int r = 0; r < 8; r++) {
                    float4 x4 = *(const float4*)&xb[r * 68 + 4 * d4];
                    u64 xl = lo2(x4), xh = hi2(x4);
                    ffma2(aa[r], al, xl); ffma2(aa[r], ah, xh);
                    ffma2(ae[r], cl, xl); ffma2(ae[r], chh, xh);
                }
            }
            float be = et_b[cp];
            float lg[8];
            float lm = -3.4e38f;
#pragma unroll
            for (int r = 0; r < 8; r++) {
                lg[r] = red2(aa[r]);
                int m = m0 + rg * 8 + r;
                if (m < NM) {
                    size_t o = ((size_t)b * NM + m) * 128;
                    d_logits[o + cp] = lg[r];
                    d_etr[o + cp]    = red2(ae[r]) + be;
                    lm = fmaxf(lm, lg[r]);
                }
            }
            float ls = 0.f;
#pragma unroll
            for (int r = 0; r < 8; r++) {
                int m = m0 + rg * 8 + r;
                if (m < NM) ls += expf(lg[r] - lm);
            }
            redm[cp * 2 + rg] = lm;
            reds[cp * 2 + rg] = ls;
        } else {
            int tt = t - 256;
            c2cp = tt & 63; c2rg = (tt >> 6) & 1; c2kh = tt >> 7;
            const float* wn0 = Ms + c2cp * 132 + c2kh * 64;
            const float* wn1 = Ms + (c2cp + 64) * 132 + c2kh * 64;
            const float* xb = nds + c2rg * 8 * 128 + c2kh * 64;
#pragma unroll
            for (int d4 = 0; d4 < 16; d4++) {
                float4 a4 = *(const float4*)&wn0[4 * d4];
                float4 b4 = *(const float4*)&wn1[4 * d4];
                u64 al = lo2(a4), ah = hi2(a4), bl = lo2(b4), bh = hi2(b4);
#pragma unroll
                for (int r = 0; r < 8; r++) {
                    float4 x4 = *(const float4*)&xb[r * 128 + 4 * d4];
                    u64 xl = lo2(x4), xh = hi2(x4);
                    ffma2(an0[r], al, xl); ffma2(an0[r], ah, xh);
                    ffma2(an1[r], bl, xl); ffma2(an1[r], bh, xh);
                }
            }
            if (c2kh == 1) {
#pragma unroll
                for (int r = 0; r < 8; r++) {
                    int rw = c2rg * 8 + r;
                    pbuf[rw * 128 + c2cp]      = red2(an0[r]);
                    pbuf[rw * 128 + c2cp + 64] = red2(an1[r]);
                }
            }
        }
        __syncthreads();

        // C2 finalize (kh==0 half) + softmax partial combine
        if (t >= 256 && c2kh == 0) {
            float bn0 = nt_b[c2cp], bn1 = nt_b[c2cp + 64];
#pragma unroll
            for (int r = 0; r < 8; r++) {
                int rw = c2rg * 8 + r;
                int m = m0 + rw;
                if (m < NM) {
                    size_t o = ((size_t)b * NM + m) * 128;
                    d_ntr[o + c2cp]      = red2(an0[r]) + pbuf[rw * 128 + c2cp] + bn0;
                    d_ntr[o + c2cp + 64] = red2(an1[r]) + pbuf[rw * 128 + c2cp + 64] + bn1;
                }
            }
        }
        if (t < 128) {
            int i = t;
            float m = fmaxf(redm[i * 2], redm[i * 2 + 1]);
            float s = reds[i * 2] * expf(redm[i * 2] - m)
                    + reds[i * 2 + 1] * expf(redm[i * 2 + 1] - m);
            d_pm[(b * nblk + ch) * 128 + i] = m;
            d_ps[(b * nblk + ch) * 128 + i] = s;
        }
    }
}

// ---------------------------------------------------------------------------
// K5: softmax combine + alpha + v + h1 gemm/gelu + h2 gemm + stores.
// h1 and h2 now on all 512 threads via kh4 split (partials in pbuf+tr).
// grid = B*nblk, block = 512, smem 51200 floats (200 KB).
// ---------------------------------------------------------------------------
__global__ void __launch_bounds__(512)
k5(const float* __restrict__ h1_w, const float* __restrict__ h1_b,
   const float* __restrict__ h2_w, const float* __restrict__ h2_b,
   float* __restrict__ out_et, float* __restrict__ out_tmp,
   float* __restrict__ out_node, int N, int nblk, float scaler) {
    extern __shared__ float sm[];
    float* H    = sm;                 // 33280 (h1_w, later h2_w)
    float* v    = H + 33280;          // 4160 (16x260)
    float* als  = v + 4160;           // 2048
    float* pbuf = als + 2048;         // 2048 (logits stage -> kh1 partials)
    float* tr   = pbuf + 2048;        // 4096 (etr|ntr stage -> kh2/kh3 partials)
    float* mxs  = tr + 4096;          // 128
    float* invs = mxs + 128;          // 128
    float* redm = invs + 128;         // 512
    float* reds = redm + 512;         // 512
    float* gs   = reds + 512;         // 2112 (16x132)
    float* qo   = gs + 2112;          // 2176 (128x17)

    int b  = blockIdx.x / nblk;
    int m0 = (blockIdx.x % nblk) * 16;
    int t  = threadIdx.x;
    int NM = N - 1;

    // ---- g0 = logits -> pbuf ----
    {
        int r = t >> 5, d4 = t & 31;
        int m = m0 + r;
        cpa16z(smadr(&pbuf[r * 128 + 4 * d4]),
               &d_logits[((size_t)b * NM + (m < NM ? m : 0)) * 128 + 4 * d4],
               m < NM);
    }
    CP_COMMIT();
    // ---- g1 = etr + ntr -> tr ----
#pragma unroll
    for (int q = t; q < 1024; q += 512) {
        int half = q >> 9, r = (q >> 5) & 15, d4 = q & 31;
        int m = m0 + r;
        size_t o = ((size_t)b * NM + (m < NM ? m : 0)) * 128 + 4 * d4;
        const float* src = half ? &d_ntr[o] : &d_etr[o];
        cpa16z(smadr(&tr[half * 2048 + r * 128 + 4 * d4]), src, m < NM);
    }
    CP_COMMIT();
    // ---- g2 = h1_w -> H ----
#pragma unroll
    for (int q = t; q < 8192; q += 512) {
        int i = q >> 6, d4 = q & 63;
        cpa16(smadr(&H[i * 260 + 4 * d4]), ((const float4*)h1_w) + q);
    }
    CP_COMMIT();

    // ---- softmax combine ----
    {
        int i = t & 127, cg = t >> 7;
        float m = -3.4e38f, s = 0.f;
        for (int chh = cg; chh < nblk; chh += 4) {
            float pm = d_pm[(b * nblk + chh) * 128 + i];
            float ps = d_ps[(b * nblk + chh) * 128 + i];
            float nm = fmaxf(m, pm);
            s = s * expf(m - nm) + ps * expf(pm - nm);
            m = nm;
        }
        redm[i * 4 + cg] = m;
        reds[i * 4 + cg] = s;
    }
    __syncthreads();
    if (t < 128) {
        int i = t;
        float m = -3.4e38f;
#pragma unroll
        for (int g = 0; g < 4; g++) m = fmaxf(m, redm[i * 4 + g]);
        float s = 0.f;
#pragma unroll
        for (int g = 0; g < 4; g++) s += reds[i * 4 + g] * expf(redm[i * 4 + g] - m);
        mxs[i]  = m;
        invs[i] = 1.f / s;
    }
    CP_WAIT(2);          // g0 (logits) complete
    __syncthreads();

    // ---- alpha ----
#pragma unroll
    for (int q = t; q < 2048; q += 512) {
        int r = q >> 7, i = q & 127;
        int m = m0 + r;
        float a = 0.f;
        if (m < NM) a = expf(pbuf[q] - mxs[i]) * invs[i];
        als[q] = a;
    }
    CP_WAIT(1);          // g1 (etr/ntr) complete
    __syncthreads();

    // ---- v = [etr*a | ntr*a] ----
#pragma unroll
    for (int q = t; q < 4096; q += 512) {
        int r = q >> 8, d = q & 255;
        int dd = d & 127;
        v[r * 260 + d] = tr[(d < 128 ? 0 : 2048) + r * 128 + dd] * als[r * 128 + dd];
    }
    CP_WAIT(0);          // g2 (h1_w) complete
    __syncthreads();

    // ---- et_p store (fire-and-forget, all threads) ----
#pragma unroll
    for (int q = t; q < 2048; q += 512) {
        int i = q >> 4, mr = q & 15;
        int m = m0 + mr;
        if (m < NM) out_et[((size_t)b * 128 + i) * NM + m] = v[mr * 260 + i];
    }

    // ---- h1 GEMM: 512 threads, 2 cols x 8 rows x kh4 ----
    {
        int cp = t & 63, rg = (t >> 6) & 1, kh = t >> 7;   // kh 0..3
        u64 a0[8] = {0,0,0,0,0,0,0,0}, a1[8] = {0,0,0,0,0,0,0,0};
        const float* w0p = H + cp * 260 + kh * 64;
        const float* w1p = H + (cp + 64) * 260 + kh * 64;
        const float* vb  = v + rg * 8 * 260 + kh * 64;
#pragma unroll
        for (int d4 = 0; d4 < 16; d4++) {
            float4 w0 = *(const float4*)&w0p[4 * d4];
            float4 w1 = *(const float4*)&w1p[4 * d4];
            u64 w0l = lo2(w0), w0h = hi2(w0), w1l = lo2(w1), w1h = hi2(w1);
#pragma unroll
            for (int r = 0; r < 8; r++) {
                float4 x4 = *(const float4*)&vb[r * 260 + 4 * d4];
                u64 xl = lo2(x4), xh = hi2(x4);
                ffma2(a0[r], w0l, xl); ffma2(a0[r], w0h, xh);
                ffma2(a1[r], w1l, xl); ffma2(a1[r], w1h, xh);
            }
        }
        if (kh > 0) {
            float* dst = (kh == 1) ? pbuf : tr + (kh - 2) * 2048;
#pragma unroll
            for (int r = 0; r < 8; r++) {
                int rw = rg * 8 + r;
                dst[rw * 128 + cp]      = red2(a0[r]);
                dst[rw * 128 + cp + 64] = red2(a1[r]);
            }
        }
        __syncthreads();
        if (kh == 0) {
            float b0 = h1_b[cp], b1 = h1_b[cp + 64];
#pragma unroll
            for (int r = 0; r < 8; r++) {
                int rw = rg * 8 + r;
                int m = m0 + rw;
                float g0 = red2(a0[r]) + pbuf[rw * 128 + cp] + tr[rw * 128 + cp]
                         + tr[2048 + rw * 128 + cp] + b0;
                float g1 = red2(a1[r]) + pbuf[rw * 128 + cp + 64] + tr[rw * 128 + cp + 64]
                         + tr[2048 + rw * 128 + cp + 64] + b1;
                gs[rw * 132 + cp]      = (m < NM) ? geluf(g0) : 0.f;
                gs[rw * 132 + cp + 64] = (m < NM) ? geluf(g1) : 0.f;
            }
        } else {
            // g3: prefetch h2_w into H (all h1 reads of H done at sync above)
#pragma unroll
            for (int q = t - 128; q < 4096; q += 384) {
                int i = q >> 5, d4 = q & 31;
                cpa16(smadr(&H[i * 132 + 4 * d4]), ((const float4*)h2_w) + q);
            }
        }
        CP_COMMIT();
        CP_WAIT(0);      // g3 (h2_w) complete
        __syncthreads();
    }

    // ---- h2 GEMM: 512 threads, 2 cols x 8 rows x kh4 (k=32 each) ----
    {
        int cp = t & 63, rg = (t >> 6) & 1, kh = t >> 7;
        u64 a0[8] = {0,0,0,0,0,0,0,0}, a1[8] = {0,0,0,0,0,0,0,0};
        const float* w0p = H + cp * 132 + kh * 32;
        const float* w1p = H + (cp + 64) * 132 + kh * 32;
        const float* gb  = gs + rg * 8 * 132 + kh * 32;
#pragma unroll
        for (int d4 = 0; d4 < 8; d4++) {
            float4 w0 = *(const float4*)&w0p[4 * d4];
            float4 w1 = *(const float4*)&w1p[4 * d4];
            u64 w0l = lo2(w0), w0h = hi2(w0), w1l = lo2(w1), w1h = hi2(w1);
#pragma unroll
            for (int r = 0; r < 8; r++) {
                float4 x4 = *(const float4*)&gb[r * 132 + 4 * d4];
                u64 xl = lo2(x4), xh = hi2(x4);
                ffma2(a0[r], w0l, xl); ffma2(a0[r], w0h, xh);
                ffma2(a1[r], w1l, xl); ffma2(a1[r], w1h, xh);
            }
        }
        if (kh > 0) {
            float* dst = (kh == 1) ? pbuf : tr + (kh - 2) * 2048;
#pragma unroll
            for (int r = 0; r < 8; r++) {
                int rw = rg * 8 + r;
                dst[rw * 128 + cp]      = red2(a0[r]);
                dst[rw * 128 + cp + 64] = red2(a1[r]);
            }
        }
        __syncthreads();
        if (kh == 0) {
            float b0 = h2_b[cp], b1 = h2_b[cp + 64];
#pragma unroll
            for (int r = 0; r < 8; r++) {
                int rw = rg * 8 + r;
                int m = m0 + rw;
                float s0 = red2(a0[r]) + pbuf[rw * 128 + cp] + tr[rw * 128 + cp]
                         + tr[2048 + rw * 128 + cp] + b0;
                float s1 = red2(a1[r]) + pbuf[rw * 128 + cp + 64] + tr[rw * 128 + cp + 64]
                         + tr[2048 + rw * 128 + cp + 64] + b1;
                qo[cp * 17 + rw]        = (m < NM) ? s0 : 0.f;
                qo[(cp + 64) * 17 + rw] = (m < NM) ? s1 : 0.f;
            }
        }
        __syncthreads();
    }

#pragma unroll
    for (int q = t; q < 2048; q += 512) {
        int i = q >> 4, mr = q & 15;
        int m = m0 + mr;
        if (m < NM) out_tmp[((size_t)b * 128 + i) * NM + m] = qo[i * 17 + mr];
    }
    if (t < 128) {
        int i = t;
        float s = 0.f;
#pragma unroll
        for (int mr = 0; mr < 16; mr++) s += qo[i * 17 + mr];
        atomicAdd(&out_node[b * 128 + i], s * scaler);
    }
}

// ---------------------------------------------------------------------------
extern "C" void kernel_launch(void* const* d_in, const int* in_sizes, int n_in,
                              void* d_out, int out_size) {
    const float* node = (const float*)d_in[0];
    const float* edge = (const float*)d_in[1];
    const float* emb  = (const float*)d_in[2];
    const float* Wq_w = (const float*)d_in[3];
    const float* Wq_b = (const float*)d_in[4];
    const float* Wk_w = (const float*)d_in[5];
    const float* Wk_b = (const float*)d_in[6];
    const float* Wew  = (const float*)d_in[7];
    const float* Web  = (const float*)d_in[8];
    const float* Wa   = (const float*)d_in[9];
    const float* nt_w = (const float*)d_in[10];
    const float* nt_b = (const float*)d_in[11];
    const float* et_w = (const float*)d_in[12];
    const float* et_b = (const float*)d_in[13];
    const float* h1_w = (const float*)d_in[14];
    const float* h1_b = (const float*)d_in[15];
    const float* h2_w = (const float*)d_in[16];
    const float* h2_b = (const float*)d_in[17];

    long n_node = in_sizes[0];
    long n_edge = in_sizes[1];
    int N = (int)((2L * n_edge) / n_node);   // 512
    int B = (int)(n_node / ((long)N * 128)); // 4
    int NM = N - 1;
    int nblk = (NM + 15) / 16;               // 32

    float* out      = (float*)d_out;
    float* out_node = out;
    float* out_tmp  = out + (size_t)B * 128;
    float* out_et   = out_tmp + (size_t)B * 128 * NM;

    const int SM23 = 52928 * 4;
    const int SM5  = 51200 * 4;

    cudaFuncSetAttribute(k23, cudaFuncAttributeMaxDynamicSharedMemorySize, SM23);
    cudaFuncSetAttribute(k5,  cudaFuncAttributeMaxDynamicSharedMemorySize, SM5);

    float scaler = 2.0f / sqrtf(128.0f);

    k1_fold<<<128, 512>>>(node, Wq_w, Wq_b, Wk_w, Wk_b, out_node, B, N);
    k23<<<B * nblk, 512, SM23>>>(node, edge, emb, Wew, Web, Wa,
                                 nt_w, nt_b, et_w, et_b, N, nblk);
    k5<<<B * nblk, 512, SM5>>>(h1_w, h1_b, h2_w, h2_b,
                               out_et, out_tmp, out_node, N, nblk, scaler);
}